// round 1
// baseline (speedup 1.0000x reference)
#include <cuda_runtime.h>
#include <math.h>

#define B   4
#define T   4
#define BT  16
#define C   320
#define HW  1600
#define THRESH 0.95f
#define NEGV  -1e9f
#define EPS   1e-12f

// Scratch (device globals; no runtime allocation)
__device__ float g_S[(size_t)BT * HW * HW];      // logits -> probs (in place)
__device__ float g_qnorm[B * HW];                // clamped ||q_p||
__device__ float g_knorm[BT * HW];               // clamped ||k_j||
__device__ int   g_colmask[BT * HW];             // mask_qk

// ---------------- norms ----------------
__global__ void qnorm_kernel(const float* __restrict__ q) {
    int i = blockIdx.x * blockDim.x + threadIdx.x;
    if (i >= B * HW) return;
    int b = i / HW, p = i % HW;
    const float* base = q + (size_t)b * C * HW + p;
    float s = 0.f;
    #pragma unroll 8
    for (int c = 0; c < C; c++) { float v = base[(size_t)c * HW]; s += v * v; }
    g_qnorm[i] = fmaxf(sqrtf(s), EPS);
}

__global__ void knorm_kernel(const float* __restrict__ k) {
    int i = blockIdx.x * blockDim.x + threadIdx.x;
    if (i >= BT * HW) return;
    int bt = i / HW, p = i % HW;
    const float* base = k + (size_t)bt * C * HW + p;
    float s = 0.f;
    #pragma unroll 8
    for (int c = 0; c < C; c++) { float v = base[(size_t)c * HW]; s += v * v; }
    g_knorm[i] = fmaxf(sqrtf(s), EPS);
}

// ---------------- QK GEMM: S[p,j] = sum_c q[c,p] * k[c,j] ----------------
// Global layout is [K=c][M/N] (k-major), so tiles load straight into [k][m] smem.
#define QK_TILE 64
#define QK_KT   16

__global__ __launch_bounds__(256) void qk_kernel(const float* __restrict__ q,
                                                 const float* __restrict__ kk) {
    __shared__ float As[QK_KT][QK_TILE];
    __shared__ float Bs[QK_KT][QK_TILE];
    int bt = blockIdx.z;
    int b  = bt >> 2;                 // T == 4
    int p0 = blockIdx.y * QK_TILE;
    int j0 = blockIdx.x * QK_TILE;
    const float* A  = q  + (size_t)b  * C * HW;   // A[c][p]
    const float* Bm = kk + (size_t)bt * C * HW;   // B[c][j]
    int t  = threadIdx.x;
    int tx = t & 15, ty = t >> 4;

    float acc[4][4] = {};

    for (int kt = 0; kt < C; kt += QK_KT) {
        #pragma unroll
        for (int r = 0; r < 4; r++) {
            int idx = t + r * 256;
            int kr  = idx >> 6;       // 0..15
            int m   = idx & 63;
            As[kr][m] = A [(size_t)(kt + kr) * HW + p0 + m];
            Bs[kr][m] = Bm[(size_t)(kt + kr) * HW + j0 + m];
        }
        __syncthreads();
        #pragma unroll
        for (int k = 0; k < QK_KT; k++) {
            float4 a = *(const float4*)&As[k][ty * 4];
            float4 c4 = *(const float4*)&Bs[k][tx * 4];
            float av[4] = {a.x, a.y, a.z, a.w};
            float bv[4] = {c4.x, c4.y, c4.z, c4.w};
            #pragma unroll
            for (int i = 0; i < 4; i++)
                #pragma unroll
                for (int j = 0; j < 4; j++)
                    acc[i][j] += av[i] * bv[j];
        }
        __syncthreads();
    }

    float* Sbase = g_S + (size_t)bt * HW * HW;
    #pragma unroll
    for (int i = 0; i < 4; i++) {
        float4 v = make_float4(acc[i][0], acc[i][1], acc[i][2], acc[i][3]);
        *(float4*)&Sbase[(size_t)(p0 + ty * 4 + i) * HW + j0 + tx * 4] = v;
    }
}

// ---------------- mask_qk: column-any of hit ----------------
__global__ void colmask_kernel() {
    int j  = blockIdx.x * blockDim.x + threadIdx.x;
    int bt = blockIdx.y;
    if (j >= HW) return;
    int b = bt >> 2;
    float th = THRESH * g_knorm[bt * HW + j];
    const float* Sp = g_S + (size_t)bt * HW * HW + j;
    int hit = 0;
    for (int p = 0; p < HW; p++) {
        float s  = Sp[(size_t)p * HW];
        float qn = g_qnorm[b * HW + p];
        hit |= (s >= th * qn);
    }
    g_colmask[bt * HW + j] = hit;
}

// ---------------- per-row: mask_kq, logit select, softmax in place ----------------
__global__ __launch_bounds__(256) void softmax_kernel() {
    __shared__ float buf[HW];
    __shared__ float r1[256];
    __shared__ float r2[256];
    __shared__ int   r3[256];

    int p  = blockIdx.x;
    int bt = blockIdx.y;
    int b  = bt >> 2;
    float* row = g_S + (size_t)bt * HW * HW + (size_t)p * HW;
    float qn = g_qnorm[b * HW + p];
    int t = threadIdx.x;

    float msim = -1e30f, msp = -1e30f;
    int hit = 0;
    for (int j = t; j < HW; j += 256) {
        float s   = row[j];
        float kn  = g_knorm[bt * HW + j];
        float sim = s / (qn * kn);
        buf[j] = sim;
        hit |= (sim >= THRESH);
        msim = fmaxf(msim, sim);
        float sl = g_colmask[bt * HW + j] ? NEGV : s;
        msp = fmaxf(msp, sl);
    }
    r1[t] = msim; r2[t] = msp; r3[t] = hit;
    __syncthreads();
    for (int s = 128; s > 0; s >>= 1) {
        if (t < s) {
            r1[t] = fmaxf(r1[t], r1[t + s]);
            r2[t] = fmaxf(r2[t], r2[t + s]);
            r3[t] |= r3[t + s];
        }
        __syncthreads();
    }
    int   use_dense = r3[0];
    float m = use_dense ? r1[0] : r2[0];

    float lsum = 0.f;
    for (int j = t; j < HW; j += 256) {
        float l;
        if (use_dense) l = buf[j];
        else           l = g_colmask[bt * HW + j] ? NEGV : row[j];
        float e = __expf(l - m);
        buf[j] = e;
        lsum += e;
    }
    r1[t] = lsum;
    __syncthreads();
    for (int s = 128; s > 0; s >>= 1) {
        if (t < s) r1[t] += r1[t + s];
        __syncthreads();
    }
    float inv = 1.f / r1[0];
    for (int j = t; j < HW; j += 256) row[j] = buf[j] * inv;
}

// ---------------- PV GEMM: Out[c,p] = sum_j V[c,j] * P[p,j] ----------------
// Both operands are [row][k] in global -> transpose on smem store so k is the
// fast smem index; pad stride to 68 floats (16B aligned rows, mild write conflicts).
#define PV_KT     32
#define PV_STRIDE 68

__global__ __launch_bounds__(256) void pv_kernel(const float* __restrict__ v,
                                                 float* __restrict__ out) {
    __shared__ float Vs[PV_KT][PV_STRIDE];
    __shared__ float Ps[PV_KT][PV_STRIDE];
    int bt = blockIdx.z;
    int c0 = blockIdx.y * 64;
    int p0 = blockIdx.x * 64;
    const float* V = v   + (size_t)bt * C * HW;     // V[c][j]
    const float* P = g_S + (size_t)bt * HW * HW;    // P[p][j]
    int t  = threadIdx.x;
    int tx = t & 15, ty = t >> 4;

    float acc[4][4] = {};

    for (int j0 = 0; j0 < HW; j0 += PV_KT) {
        #pragma unroll
        for (int r = 0; r < 2; r++) {
            int vi  = t + r * 256;
            int row = vi >> 3;        // 0..63
            int jg  = vi & 7;         // float4 group within 32-wide k tile
            float4 a = *(const float4*)&V[(size_t)(c0 + row) * HW + j0 + jg * 4];
            Vs[jg * 4 + 0][row] = a.x;
            Vs[jg * 4 + 1][row] = a.y;
            Vs[jg * 4 + 2][row] = a.z;
            Vs[jg * 4 + 3][row] = a.w;
            float4 pb = *(const float4*)&P[(size_t)(p0 + row) * HW + j0 + jg * 4];
            Ps[jg * 4 + 0][row] = pb.x;
            Ps[jg * 4 + 1][row] = pb.y;
            Ps[jg * 4 + 2][row] = pb.z;
            Ps[jg * 4 + 3][row] = pb.w;
        }
        __syncthreads();
        #pragma unroll
        for (int k = 0; k < PV_KT; k++) {
            float4 a  = *(const float4*)&Vs[k][ty * 4];
            float4 c4 = *(const float4*)&Ps[k][tx * 4];
            float av[4] = {a.x, a.y, a.z, a.w};
            float bv[4] = {c4.x, c4.y, c4.z, c4.w};
            #pragma unroll
            for (int i = 0; i < 4; i++)
                #pragma unroll
                for (int j = 0; j < 4; j++)
                    acc[i][j] += av[i] * bv[j];
        }
        __syncthreads();
    }

    float* O = out + (size_t)bt * C * HW;
    #pragma unroll
    for (int i = 0; i < 4; i++) {
        float4 w = make_float4(acc[i][0], acc[i][1], acc[i][2], acc[i][3]);
        *(float4*)&O[(size_t)(c0 + ty * 4 + i) * HW + p0 + tx * 4] = w;
    }
}

// ---------------- launch ----------------
extern "C" void kernel_launch(void* const* d_in, const int* in_sizes, int n_in,
                              void* d_out, int out_size) {
    const float* q = (const float*)d_in[0];   // [B,1,C,H,W]
    const float* k = (const float*)d_in[1];   // [B,T,C,H,W]
    const float* v = (const float*)d_in[2];   // [B,T,C,H,W]
    float* out = (float*)d_out;               // [B,T,C,H,W]

    qnorm_kernel<<<(B * HW + 255) / 256, 256>>>(q);
    knorm_kernel<<<(BT * HW + 255) / 256, 256>>>(k);

    dim3 gqk(HW / QK_TILE, HW / QK_TILE, BT);
    qk_kernel<<<gqk, 256>>>(q, k);

    dim3 gcm((HW + 255) / 256, BT);
    colmask_kernel<<<gcm, 256>>>();

    dim3 gsm(HW, BT);
    softmax_kernel<<<gsm, 256>>>();

    dim3 gpv(HW / 64, C / 64, BT);
    pv_kernel<<<gpv, 256>>>(v, out);
}